// round 9
// baseline (speedup 1.0000x reference)
#include <cuda_runtime.h>
#include <cstdint>

// out[b,i,j,o] = x[b,2i,2j, o&31] + x[b,2i,2j+1, (o>>5)&15]
//              + x[b,2i+1,2j, 0]  + x[b,2i+1,2j+1, 0]
// (one-hot conv kernel collapses to gather-add; c2=c3=0 since C_OUT=512 < 32^2)
//
// 4 pixels per warp, loads grouped before stores: lengthens read bursts and
// write bursts 4x at the memory controller to cut read/write turnaround.

#define B_DIM 64
#define H_DIM 128
#define W_DIM 128
#define C_IN 32
#define OH 64
#define OW 64
#define C_OUT 512
#define NPIX (B_DIM * OH * OW)        // 262144 output pixels
#define PPW 4                         // pixels per warp
#define NWARPS (NPIX / PPW)           // 65536 warps

__device__ __forceinline__ float ld_keep(const float* p, uint64_t pol) {
    float v;
    asm volatile("ld.global.L2::cache_hint.f32 %0, [%1], %2;"
                 : "=f"(v) : "l"(p), "l"(pol));
    return v;
}

__device__ __forceinline__ void stg256_stream(float* ptr, uint64_t pol,
                                              float v0, float v1, float v2, float v3,
                                              float v4, float v5, float v6, float v7) {
    asm volatile(
        "st.global.L2::cache_hint.v8.f32 [%0], {%2, %3, %4, %5, %6, %7, %8, %9}, %1;"
        :: "l"(ptr), "l"(pol),
           "f"(v0), "f"(v1), "f"(v2), "f"(v3),
           "f"(v4), "f"(v5), "f"(v6), "f"(v7)
        : "memory");
}

__global__ void __launch_bounds__(256, 6)
conv2dproduct_kernel(const float* __restrict__ x, float* __restrict__ out) {
    const int w    = (blockIdx.x * blockDim.x + threadIdx.x) >> 5;
    const int lane = threadIdx.x & 31;
    if (w >= NWARPS) return;

    uint64_t pol_keep, pol_stream;
    asm("createpolicy.fractional.L2::evict_last.b64 %0, 1.0;"  : "=l"(pol_keep));
    asm("createpolicy.fractional.L2::evict_first.b64 %0, 1.0;" : "=l"(pol_stream));

    const int p0 = w * PPW;
    const unsigned FULL = 0xFFFFFFFFu;

    // ---- READ PHASE: 16 back-to-back LDGs (4 pixels x 4 loads) ----
    float a[PPW], bv[PPW], base[PPW];
#pragma unroll
    for (int t = 0; t < PPW; t++) {
        const int p = p0 + t;
        const int j = p & 63;
        const int i = (p >> 6) & 63;
        const int b = p >> 12;
        const float* px = x + ((((size_t)b * H_DIM + 2 * i) * W_DIM) + 2 * j) * C_IN;
        a[t]  = ld_keep(px + lane, pol_keep);                 // 128B line
        bv[t] = ld_keep(px + C_IN + (lane & 15), pol_keep);   // 64B
        base[t] = ld_keep(px + (size_t)W_DIM * C_IN, pol_keep)
                + ld_keep(px + (size_t)W_DIM * C_IN + C_IN, pol_keep);
    }

    // ---- WRITE PHASE: 8 back-to-back STG.256 (4 pixels x 2 chunks) ----
    // Lane covers floats 8q..8q+7 with q = 32*chunk + lane (chunk 0..1):
    //   a-channels = 8*(lane&3)..+7 (chunk-invariant), b-group g = 8*chunk+(lane>>2)
    const int jj = (lane & 3) * 8;
#pragma unroll
    for (int t = 0; t < PPW; t++) {
        float f[8];
#pragma unroll
        for (int k = 0; k < 8; k++) f[k] = __shfl_sync(FULL, a[t], jj + k);

        float* obase = out + (size_t)(p0 + t) * C_OUT + lane * 8;
#pragma unroll
        for (int chunk = 0; chunk < 2; chunk++) {
            const int g = chunk * 8 + (lane >> 2);
            const float s = __shfl_sync(FULL, bv[t], g) + base[t];
            stg256_stream(obase + chunk * 256, pol_stream,
                          f[0] + s, f[1] + s, f[2] + s, f[3] + s,
                          f[4] + s, f[5] + s, f[6] + s, f[7] + s);
        }
    }
}

extern "C" void kernel_launch(void* const* d_in, const int* in_sizes, int n_in,
                              void* d_out, int out_size) {
    const float* x = (const float*)d_in[0];
    float* out = (float*)d_out;

    const int total_threads = NWARPS * 32;
    const int block = 256;
    const int grid = (total_threads + block - 1) / block;  // 8192
    conv2dproduct_kernel<<<grid, block>>>(x, out);
}

// round 10
// speedup vs baseline: 1.1446x; 1.1446x over previous
#include <cuda_runtime.h>
#include <cstdint>

// out[b,i,j,o] = x[b,2i,2j, o&31] + x[b,2i,2j+1, (o>>5)&15]
//              + x[b,2i+1,2j, 0]  + x[b,2i+1,2j+1, 0]
// (one-hot conv kernel collapses to gather-add; c2=c3=0 since C_OUT=512 < 32^2)
//
// Converged shape: 1 pixel per warp, 4 coalesced LDGs, 8 shuffles,
// 2x STG.256 (evict_first). DRAM-traffic-minimal: 512 MiB compulsory write
// + 64 MiB sector-minimal read at ~6.29 TB/s achieved.

#define B_DIM 64
#define H_DIM 128
#define W_DIM 128
#define C_IN 32
#define OH 64
#define OW 64
#define C_OUT 512
#define NPIX (B_DIM * OH * OW)  // 262144 output pixels
#define TPB 512

__device__ __forceinline__ void stg256_stream(float* ptr, uint64_t pol,
                                              float v0, float v1, float v2, float v3,
                                              float v4, float v5, float v6, float v7) {
    // 256-bit global store with evict_first L2 policy (sm_103a, PTX ISA 8.7+).
    asm volatile(
        "st.global.L2::cache_hint.v8.f32 [%0], {%2, %3, %4, %5, %6, %7, %8, %9}, %1;"
        :: "l"(ptr), "l"(pol),
           "f"(v0), "f"(v1), "f"(v2), "f"(v3),
           "f"(v4), "f"(v5), "f"(v6), "f"(v7)
        : "memory");
}

__global__ void __launch_bounds__(TPB, 4)
conv2dproduct_kernel(const float* __restrict__ x, float* __restrict__ out) {
    const int warp = (blockIdx.x * TPB + threadIdx.x) >> 5;
    const int lane = threadIdx.x & 31;
    if (warp >= NPIX) return;

    uint64_t pol_stream;
    asm("createpolicy.fractional.L2::evict_first.b64 %0, 1.0;" : "=l"(pol_stream));

    // pixel decomposition: warp = ((b*64 + i)*64 + j)
    const int j = warp & 63;
    const int i = (warp >> 6) & 63;
    const int b = warp >> 12;

    // input base: x[b][2i][2j][0]
    const size_t in_base = ((((size_t)b * H_DIM + 2 * i) * W_DIM) + 2 * j) * C_IN;
    const float* __restrict__ px = x + in_base;

    // a[lane] : top-left pixel, all 32 channels (one 128B coalesced load)
    const float a_val = __ldg(px + lane);
    // b[lane&15] : top-right pixel, channels 0..15 (64B, 2 sectors)
    const float b_val = __ldg(px + C_IN + (lane & 15));
    // base = bottom-left ch0 + bottom-right ch0 (uniform broadcast loads)
    const float base = __ldg(px + (size_t)W_DIM * C_IN)
                     + __ldg(px + (size_t)W_DIM * C_IN + C_IN);

    // Lane covers floats 8q..8q+7 with q = 32*chunk + lane (chunk 0..1).
    //   a-channels  = 8*(lane&3) .. +7   (chunk-invariant -> 8 shuffles)
    //   b-group g   = q>>2 = 8*chunk + (lane>>2)
    const unsigned FULL = 0xFFFFFFFFu;
    const int jj = (lane & 3) * 8;
    float f[8];
#pragma unroll
    for (int k = 0; k < 8; k++) f[k] = __shfl_sync(FULL, a_val, jj + k);

    float* __restrict__ obase = out + (size_t)warp * C_OUT + lane * 8;

#pragma unroll
    for (int chunk = 0; chunk < 2; chunk++) {
        const int g = chunk * 8 + (lane >> 2);           // 0..15
        const float s = __shfl_sync(FULL, b_val, g) + base;
        stg256_stream(obase + chunk * 256, pol_stream,
                      f[0] + s, f[1] + s, f[2] + s, f[3] + s,
                      f[4] + s, f[5] + s, f[6] + s, f[7] + s);
    }
}

extern "C" void kernel_launch(void* const* d_in, const int* in_sizes, int n_in,
                              void* d_out, int out_size) {
    const float* x = (const float*)d_in[0];
    float* out = (float*)d_out;

    const int total_threads = NPIX * 32;      // one warp per output pixel
    const int grid = (total_threads + TPB - 1) / TPB;  // 16384
    conv2dproduct_kernel<<<grid, TPB>>>(x, out);
}